// round 4
// baseline (speedup 1.0000x reference)
#include <cuda_runtime.h>

// Fixed shapes: B=32, T=1024, D=1024. All GEMM paths are dead code:
// softmax over a singleton axis => every attention weight == 1.0, so
//   context[b,d] = sum_t values[b,t,d],  aw = 1.0,  cov[b,t] = t.
#define BB 32
#define TT 1024
#define DD 1024
#define D4 256                       // float4 per row (4KB rows)
#define NCHUNK 32                    // chunks per batch
#define TC (TT / NCHUNK)             // 32 rows per chunk (128KB contiguous)

// Output layout (98304 floats):
//   [0, B*D)             context
//   [B*D, B*D+B*T)       attention_weights (all 1.0)
//   [B*D+B*T, end)       coverage (cov[b,t] = t)

__device__ float4 g_partial[BB * NCHUNK * D4];   // 4 MB scratch

// ---------------- Stage 1: streaming partial sums + aw/cov fill -------------
__global__ void stage1_kernel(const float4* __restrict__ vals,
                              float* __restrict__ out) {
    const int c   = blockIdx.x;      // 0..31 chunk
    const int b   = blockIdx.y;      // 0..31 batch
    const int tid = threadIdx.x;     // 0..255 (one float4 column)

    const float4* __restrict__ p = vals + ((size_t)b * TT + (size_t)c * TC) * D4 + tid;

    float x = 0.f, y = 0.f, z = 0.f, w = 0.f;
    // Explicitly batched 4-deep loads: forces >=4 LDG.128 in flight per thread
    // (defeats ptxas's load-serialize at 32 regs).
#pragma unroll
    for (int i = 0; i < TC / 4; ++i) {
        float4 v0 = p[0 * (size_t)D4];
        float4 v1 = p[1 * (size_t)D4];
        float4 v2 = p[2 * (size_t)D4];
        float4 v3 = p[3 * (size_t)D4];
        p += 4 * (size_t)D4;
        x += v0.x; y += v0.y; z += v0.z; w += v0.w;
        x += v1.x; y += v1.y; z += v1.z; w += v1.w;
        x += v2.x; y += v2.y; z += v2.z; w += v2.w;
        x += v3.x; y += v3.y; z += v3.z; w += v3.w;
    }
    g_partial[(b * NCHUNK + c) * D4 + tid] = make_float4(x, y, z, w);

    // aw/cov fill: 1024 blocks x 8 float4 per array (hidden in the stream).
    const int blk = b * NCHUNK + c;  // 0..1023
    if (tid < 8) {
        float4* aw4 = reinterpret_cast<float4*>(out + BB * DD);
        aw4[blk * 8 + tid] = make_float4(1.f, 1.f, 1.f, 1.f);
    } else if (tid >= 32 && tid < 40) {
        float4* cov4 = reinterpret_cast<float4*>(out + BB * DD + BB * TT);
        const int q = blk * 8 + (tid - 32);      // float4 index into [B,T]
        const int t0 = (q * 4) & (TT - 1);
        cov4[q] = make_float4((float)t0, (float)(t0 + 1), (float)(t0 + 2), (float)(t0 + 3));
    }
}

// ---------------- Stage 2: context reduce only (L2-resident) ----------------
__global__ void finalize_kernel(float* __restrict__ out) {
    const int idx = blockIdx.x * blockDim.x + threadIdx.x;  // 0..8191 float4
    const int b  = idx >> 8;          // /256
    const int d4 = idx & 255;

    const float4* part = g_partial + (size_t)b * NCHUNK * D4 + d4;
    float x = 0.f, y = 0.f, z = 0.f, w = 0.f;
#pragma unroll
    for (int cc = 0; cc < NCHUNK; ++cc) {        // fixed order -> deterministic
        float4 v = part[(size_t)cc * D4];
        x += v.x; y += v.y; z += v.z; w += v.w;
    }
    reinterpret_cast<float4*>(out)[idx] = make_float4(x, y, z, w);
}

extern "C" void kernel_launch(void* const* d_in, const int* in_sizes, int n_in,
                              void* d_out, int out_size) {
    // Inputs: query, values, W1, b1, W2, b2, W3, b3, V, bV
    const float4* values = (const float4*)d_in[1];
    float* out = (float*)d_out;

    dim3 grid1(NCHUNK, BB);                      // 1024 blocks
    stage1_kernel<<<grid1, D4>>>(values, out);

    finalize_kernel<<<BB, D4>>>(out);            // 32 blocks x 256 thr = 8192 float4
}

// round 5
// speedup vs baseline: 1.0850x; 1.0850x over previous
#include <cuda_runtime.h>

// Fixed shapes: B=32, T=1024, D=1024. All GEMM paths are dead code:
// softmax over a singleton axis => every attention weight == 1.0, so
//   context[b,d] = sum_t values[b,t,d],  aw = 1.0,  cov[b,t] = t.
#define BB 32
#define TT 1024
#define DD 1024
#define D4 256                       // float4 per row (4KB rows)
#define NCHUNK 32                    // chunks per batch
#define TC (TT / NCHUNK)             // 32 rows per chunk (128KB contiguous)

// Output layout (98304 floats):
//   [0, B*D)             context
//   [B*D, B*D+B*T)       attention_weights (all 1.0)
//   [B*D+B*T, end)       coverage (cov[b,t] = t)

__device__ float4 g_partial[BB * NCHUNK * D4];   // 4 MB scratch

// ---------------- Stage 1: streaming partial sums + aw/cov fill -------------
__global__ void stage1_kernel(const float4* __restrict__ vals,
                              float* __restrict__ out) {
    const int c   = blockIdx.x;      // 0..31 chunk
    const int b   = blockIdx.y;      // 0..31 batch
    const int tid = threadIdx.x;     // 0..255 (one float4 column)

    const float4* __restrict__ p = vals + ((size_t)b * TT + (size_t)c * TC) * D4 + tid;

    // 8 independent loads per iteration -> 8 LDG.128 in flight per thread.
    float x = 0.f, y = 0.f, z = 0.f, w = 0.f;
#pragma unroll
    for (int i = 0; i < TC / 8; ++i) {
        float4 v0 = p[0 * (size_t)D4];
        float4 v1 = p[1 * (size_t)D4];
        float4 v2 = p[2 * (size_t)D4];
        float4 v3 = p[3 * (size_t)D4];
        float4 v4 = p[4 * (size_t)D4];
        float4 v5 = p[5 * (size_t)D4];
        float4 v6 = p[6 * (size_t)D4];
        float4 v7 = p[7 * (size_t)D4];
        p += 8 * (size_t)D4;
        x += v0.x; y += v0.y; z += v0.z; w += v0.w;
        x += v1.x; y += v1.y; z += v1.z; w += v1.w;
        x += v2.x; y += v2.y; z += v2.z; w += v2.w;
        x += v3.x; y += v3.y; z += v3.z; w += v3.w;
        x += v4.x; y += v4.y; z += v4.z; w += v4.w;
        x += v5.x; y += v5.y; z += v5.z; w += v5.w;
        x += v6.x; y += v6.y; z += v6.z; w += v6.w;
        x += v7.x; y += v7.y; z += v7.z; w += v7.w;
    }
    g_partial[(b * NCHUNK + c) * D4 + tid] = make_float4(x, y, z, w);

    // aw/cov fill: 1024 blocks x 8 float4 per array (hidden in the stream).
    const int blk = b * NCHUNK + c;  // 0..1023
    if (tid < 8) {
        float4* aw4 = reinterpret_cast<float4*>(out + BB * DD);
        aw4[blk * 8 + tid] = make_float4(1.f, 1.f, 1.f, 1.f);
    } else if (tid >= 32 && tid < 40) {
        float4* cov4 = reinterpret_cast<float4*>(out + BB * DD + BB * TT);
        const int q = blk * 8 + (tid - 32);      // float4 index into [B,T]
        const int t0 = (q * 4) & (TT - 1);
        cov4[q] = make_float4((float)t0, (float)(t0 + 1), (float)(t0 + 2), (float)(t0 + 3));
    }
}

// ---------------- Stage 2: context reduce (256 blocks, L2-resident) ---------
// Block = (d-slice ds of 32 float4, batch b). Threads: col = tid&31 (d4 within
// slice), cl = tid>>5 (chunk lane, 0..7). Each thread sums chunks cl, cl+8,
// cl+16, cl+24 (fixed order), then tree-reduce over the 8 lanes in smem.
__global__ __launch_bounds__(256) void finalize_kernel(float* __restrict__ out) {
    const int ds = blockIdx.x;       // 0..7
    const int b  = blockIdx.y;       // 0..31
    const int tid = threadIdx.x;
    const int col = tid & 31;        // 0..31
    const int cl  = tid >> 5;        // 0..7

    const int d4 = ds * 32 + col;
    const float4* part = g_partial + (size_t)b * NCHUNK * D4 + d4;

    float4 v0 = part[(size_t)(cl +  0) * D4];
    float4 v1 = part[(size_t)(cl +  8) * D4];
    float4 v2 = part[(size_t)(cl + 16) * D4];
    float4 v3 = part[(size_t)(cl + 24) * D4];
    float x = v0.x + v1.x + v2.x + v3.x;
    float y = v0.y + v1.y + v2.y + v3.y;
    float z = v0.z + v1.z + v2.z + v3.z;
    float w = v0.w + v1.w + v2.w + v3.w;

    __shared__ float4 red[8][32];
    red[cl][col] = make_float4(x, y, z, w);
    __syncthreads();
#pragma unroll
    for (int s = 4; s > 0; s >>= 1) {
        if (cl < s) {
            float4 a = red[cl][col];
            float4 c2 = red[cl + s][col];
            red[cl][col] = make_float4(a.x + c2.x, a.y + c2.y, a.z + c2.z, a.w + c2.w);
        }
        __syncthreads();
    }
    if (cl == 0) {
        reinterpret_cast<float4*>(out)[(size_t)b * D4 + d4] = red[0][col];
    }
}

extern "C" void kernel_launch(void* const* d_in, const int* in_sizes, int n_in,
                              void* d_out, int out_size) {
    // Inputs: query, values, W1, b1, W2, b2, W3, b3, V, bV
    const float4* values = (const float4*)d_in[1];
    float* out = (float*)d_out;

    dim3 grid1(NCHUNK, BB);                      // 1024 blocks
    stage1_kernel<<<grid1, D4>>>(values, out);

    dim3 grid2(8, BB);                           // 256 blocks
    finalize_kernel<<<grid2, 256>>>(out);
}